// round 10
// baseline (speedup 1.0000x reference)
#include <cuda_runtime.h>

// APLoss, single persistent fused kernel (v7 — work stealing, small tiles):
//   s_ij = relu(1 - f_i + y_j)^2 ;  S_all[i] = sum_{j<n}, S_pos[i] = sum_{j<npos}
//   (reference: y_true = [ones(npos), zeros] -> pos set = first npos preds)
//   ua = 0.01*u_all[idx] + 0.99*S_all/N ; up likewise
//   loss = (1/(npos*N)) * sum_i (up*S_all/ua - S_pos)/ua
//
// Mainloop (exact): h = t + |t| = 2*relu(t); fma2(h,h) accumulates 4*relu^2
// (0.25 applied at deposit). y loaded as ulonglong2 -> packed pairs with no
// MOVs. First tile is static (blockIdx, speculative w.r.t. npos); further
// tiles come from a global atomic ticket so fast blocks absorb stragglers'
// work. Ticket increments per replay are deterministically `tiles`; the final
// row-finisher subtracts `tiles` (commutative, race-free across late grabs).
// Per-row completion counters run the closed-form epilogue inline.

#define QMAX    16384
#define QTILE   128
#define JTILE   256
#define NTH     256
#define QPT     4
#define JS      8               // warps per block = j slices
#define JSL     (JTILE / JS)    // 32 y per slice
#define NBLK    592
#define NROWMAX (QMAX / QTILE)
#define PADV    (-1.0e30f)

__device__ double g_Sall[QMAX];
__device__ double g_Spos[QMAX];
__device__ int    g_rowcnt[NROWMAX];
__device__ int    g_rows_done;
__device__ int    g_tick;
__device__ double g_loss;

typedef unsigned long long ull;
#define ABSM 0x7FFFFFFF7FFFFFFFull

__device__ __forceinline__ ull add2(ull a, ull b) {
    ull d; asm("add.rn.f32x2 %0,%1,%2;" : "=l"(d) : "l"(a), "l"(b)); return d;
}
__device__ __forceinline__ ull fma2(ull a, ull b, ull c) {
    ull d; asm("fma.rn.f32x2 %0,%1,%2,%3;" : "=l"(d) : "l"(a), "l"(b), "l"(c)); return d;
}
__device__ __forceinline__ ull pack2(float lo, float hi) {
    ull d; asm("mov.b64 %0,{%1,%2};" : "=l"(d) : "f"(lo), "f"(hi)); return d;
}
__device__ __forceinline__ float2 unpack2(ull v) {
    float2 r; asm("mov.b64 {%0,%1},%2;" : "=f"(r.x), "=f"(r.y) : "l"(v)); return r;
}

__device__ __forceinline__ int read_npos(const int* p, int n) {
    int v = p[0];
    if (v < 1) v = 1;
    if (v > n) v = n;
    if (v > QMAX) v = QMAX;
    return v;
}

// One 128q x 256j tile, y via warp-uniform 16B loads (packed pairs directly).
// Depends only on q0/j0/jlim/n. outp[k] = 4 * sum relu(c_k + y)^2.
__device__ __forceinline__ void tile_main(
    const float* __restrict__ y_pred, int n,
    int q0, int j0, int jlim,
    int qg, int js, float outp[QPT])
{
    ull c2[QPT];
    {
        int qb4 = q0 + qg * QPT;
        float4 cv;
        if (qb4 + QPT <= n) {
            cv = *(const float4*)(y_pred + qb4);
        } else {
            cv.x = (qb4 + 0 < n) ? y_pred[qb4 + 0] : 2.0f;
            cv.y = (qb4 + 1 < n) ? y_pred[qb4 + 1] : 2.0f;
            cv.z = (qb4 + 2 < n) ? y_pred[qb4 + 2] : 2.0f;
            cv.w = (qb4 + 3 < n) ? y_pred[qb4 + 3] : 2.0f;
        }
        float c0 = (qb4 + 0 < n) ? (1.0f - cv.x) : PADV;
        float c1 = (qb4 + 1 < n) ? (1.0f - cv.y) : PADV;
        float c2f = (qb4 + 2 < n) ? (1.0f - cv.z) : PADV;
        float c3 = (qb4 + 3 < n) ? (1.0f - cv.w) : PADV;
        c2[0] = pack2(c0, c0); c2[1] = pack2(c1, c1);
        c2[2] = pack2(c2f, c2f); c2[3] = pack2(c3, c3);
    }

    const float* base = y_pred + j0 + js * JSL;     // warp-uniform, 128B align
    ull a0[QPT], a1[QPT];
    #pragma unroll
    for (int k = 0; k < QPT; k++) { a0[k] = 0ull; a1[k] = 0ull; }

    if (j0 + JTILE <= jlim) {                       // full tile fast path
        const ulonglong2* p2 = (const ulonglong2*)base;
        #pragma unroll
        for (int u = 0; u < JSL / 4; u++) {
            ulonglong2 yv = p2[u];                  // LDG.128 -> packed pairs
            #pragma unroll
            for (int k = 0; k < QPT; k++) {
                ull t01 = add2(c2[k], yv.x);
                ull t23 = add2(c2[k], yv.y);
                ull h01 = add2(t01, t01 & ABSM);    // t + |t| = 2*relu(t)
                ull h23 = add2(t23, t23 & ABSM);
                a0[k] = fma2(h01, h01, a0[k]);      // 4*relu(t)^2
                a1[k] = fma2(h23, h23, a1[k]);
            }
        }
    } else {                                        // guarded boundary tile
        for (int u = 0; u < JSL / 4; u++) {
            int jb = j0 + js * JSL + 4 * u;
            float4 yv;
            yv.x = (jb + 0 < jlim) ? base[4 * u + 0] : PADV;
            yv.y = (jb + 1 < jlim) ? base[4 * u + 1] : PADV;
            yv.z = (jb + 2 < jlim) ? base[4 * u + 2] : PADV;
            yv.w = (jb + 3 < jlim) ? base[4 * u + 3] : PADV;
            ull y01 = pack2(yv.x, yv.y);
            ull y23 = pack2(yv.z, yv.w);
            #pragma unroll
            for (int k = 0; k < QPT; k++) {
                ull t01 = add2(c2[k], y01);
                ull t23 = add2(c2[k], y23);
                ull h01 = add2(t01, t01 & ABSM);
                ull h23 = add2(t23, t23 & ABSM);
                a0[k] = fma2(h01, h01, a0[k]);
                a1[k] = fma2(h23, h23, a1[k]);
            }
        }
    }

    #pragma unroll
    for (int k = 0; k < QPT; k++) {
        float2 v0 = unpack2(a0[k]);
        float2 v1 = unpack2(a1[k]);
        outp[k] = (v0.x + v0.y) + (v1.x + v1.y);    // = 4 * partial
    }
}

__global__ __launch_bounds__(NTH) void k_fused(
    const float* __restrict__ y_pred,
    const float* __restrict__ u_all,
    const float* __restrict__ u_pos,
    const int*   __restrict__ index_s,
    const int*   __restrict__ d_npos,
    float* __restrict__ out, int n, int jb_all, int jsh)
{
    __shared__ float  sRed[JS][QTILE];
    __shared__ double sD[JS];
    __shared__ int    sLastRow, sNextT;

    const int tid = threadIdx.x;
    const int qg  = tid & 31;
    const int js  = tid >> 5;

    // issued now, consumed only after the first mainloop
    const int npos = read_npos(d_npos, n);

    int t = blockIdx.x;           // first tile static (speculative prologue)
    while (true) {
        // ---- speculative all-tile mainloop (npos-independent for t<t_all) --
        const int qb = (jsh >= 0) ? (t >> jsh) : (t / jb_all);
        const int q0 = qb * QTILE;
        const int j0 = (t - qb * jb_all) * JTILE;

        float p[QPT];
        tile_main(y_pred, n, q0, j0, n, qg, js, p);

        // ---- npos-dependent bookkeeping ----
        const int nq        = (npos + QTILE - 1) / QTILE;
        const int t_all     = nq * jb_all;
        const int rem       = npos & (JTILE - 1);
        const int npos_base = npos - rem;
        const int tiles     = t_all + (rem ? nq : 0);
        const int target    = jb_all + (rem ? 1 : 0);

        int row = -1, rowq0 = 0;
        bool strad = false;

        if (t >= tiles) {
            // speculative tile was out of range (possible only for the
            // static first tile when blockIdx >= tiles): discard, steal below.
        } else if (t >= t_all) {                    // straddle: redo guarded
            const int qb2 = t - t_all;
            rowq0 = qb2 * QTILE;
            tile_main(y_pred, n, rowq0, npos_base, npos, qg, js, p);
            row = qb2; strad = true;
        } else if (q0 < npos) {
            row = qb; rowq0 = q0;
        }

        if (row >= 0) {
            __syncthreads();                        // protect prev sRed gather
            #pragma unroll
            for (int k = 0; k < QPT; k++)
                sRed[js][qg * QPT + k] = p[k];
            __syncthreads();

            if (tid < QTILE) {
                float s = 0.f;
                #pragma unroll
                for (int r = 0; r < JS; r++) s += sRed[r][tid];
                s *= 0.25f;                         // undo 4x (exact)
                int q = rowq0 + tid;
                if (q < npos) {
                    double sd = (double)s;
                    if (strad) {
                        atomicAdd(&g_Spos[q], sd);
                    } else {
                        atomicAdd(&g_Sall[q], sd);
                        if (j0 + JTILE <= npos)
                            atomicAdd(&g_Spos[q], sd);
                    }
                }
            }

            // row completion (thread-0 fence publishes block's deposits)
            __syncthreads();
            if (tid == 0) {
                __threadfence();
                int old = atomicAdd(&g_rowcnt[row], 1);
                sLastRow = (old == target - 1) ? 1 : 0;
            }
            __syncthreads();

            if (sLastRow) {
                __threadfence();                    // acquire peers' deposits

                const float G    = 0.99f;
                const float OMG  = 1.0f - 0.99f;
                const float invN = 1.0f / (float)n;

                double term = 0.0;
                if (tid < QTILE) {
                    int q = rowq0 + tid;
                    if (q < npos) {
                        float S_all = (float)__ldcg(&g_Sall[q]);
                        float S_pos = (float)__ldcg(&g_Spos[q]);
                        int   id    = index_s[q];
                        float ua = OMG * u_all[id] + G * (S_all * invN);
                        float up = OMG * u_pos[id] + G * (S_pos * invN);
                        float r  = 1.0f / ua;
                        term = (double)((up * S_all * r - S_pos) * r);
                        g_Sall[q] = 0.0;            // reset for next replay
                        g_Spos[q] = 0.0;
                    }
                }
                #pragma unroll
                for (int off = 16; off > 0; off >>= 1)
                    term += __shfl_down_sync(0xffffffffu, term, off);
                if (qg == 0) sD[js] = term;
                __syncthreads();
                if (tid == 0) {
                    double L = 0.0;
                    #pragma unroll
                    for (int w = 0; w < JS; w++) L += sD[w];
                    atomicAdd(&g_loss, L);
                    g_rowcnt[row] = 0;
                    __threadfence();
                    int od = atomicAdd(&g_rows_done, 1);
                    if (od == nq - 1) {             // final row finished
                        __threadfence();
                        double Lf = atomicAdd(&g_loss, 0.0);
                        out[0] = (float)(Lf / ((double)npos * (double)n));
                        atomicExch((unsigned long long*)&g_loss, 0ull);
                        atomicExch(&g_rows_done, 0);
                        // ticket reset: exactly `tiles` increments happen per
                        // replay (successful + one failed grab per working
                        // block); Sub is commutative with late failed grabs.
                        atomicSub(&g_tick, tiles);
                    }
                }
            }
        }

        // ---- steal next tile (ticket covers t >= NBLK) ----
        if (tid == 0)
            sNextT = NBLK + atomicAdd(&g_tick, 1);
        __syncthreads();
        t = sNextT;
        if (t >= tiles) break;
    }
}

extern "C" void kernel_launch(void* const* d_in, const int* in_sizes, int n_in,
                              void* d_out, int out_size) {
    const float* y_pred  = (const float*)d_in[0];
    const float* u_all   = (const float*)d_in[2];
    const float* u_pos   = (const float*)d_in[3];
    const int*   index_s = (const int*)  d_in[4];
    const int*   d_npos  = (const int*)  d_in[5];
    int n = in_sizes[0];

    int jb_all = (n + JTILE - 1) / JTILE;
    int jsh = -1;
    if ((jb_all & (jb_all - 1)) == 0) {
        jsh = 0;
        while ((1 << jsh) < jb_all) jsh++;
    }

    k_fused<<<NBLK, NTH>>>(y_pred, u_all, u_pos, index_s, d_npos,
                           (float*)d_out, n, jb_all, jsh);
}

// round 11
// speedup vs baseline: 70.9310x; 70.9310x over previous
#include <cuda_runtime.h>

// APLoss, single persistent fused kernel (v8 — race-free work stealing):
//   s_ij = relu(1 - f_i + y_j)^2 ;  S_all[i] = sum_{j<n}, S_pos[i] = sum_{j<npos}
//   (reference: y_true = [ones(npos), zeros] -> pos set = first npos preds)
//   ua = 0.01*u_all[idx] + 0.99*S_all/N ; up likewise
//   loss = (1/(npos*N)) * sum_i (up*S_all/ua - S_pos)/ua
//
// Mainloop (exact): h = t + |t| = 2*relu(t); fma2(h,h) accumulates 4*relu^2
// (0.25 applied at deposit). y staged in smem, read as ulonglong2 (LDS.128
// warp-uniform broadcast). First tile static (blockIdx — speculative w.r.t.
// npos, which is loaded in parallel); further tiles from a global ticket.
// RESET PROTOCOL (fixes R10 race): each block ends with exactly one failed
// grab, then bumps g_exit; the last exiter (old == NBLK-1) knows every grab
// of this replay has retired and plain-stores g_tick = g_exit = 0. Graph
// replays are stream-serialized, so no cross-replay race exists.
// Per-row completion counters run the closed-form epilogue inline.

#define QMAX    16384
#define QTILE   128
#define JTILE   256
#define NTH     256
#define QPT     4
#define JS      8               // warps per block = j slices
#define JSL     (JTILE / JS)    // 32 y per slice
#define NBLK    592
#define NROWMAX (QMAX / QTILE)
#define PADV    (-1.0e30f)

__device__ double g_Sall[QMAX];
__device__ double g_Spos[QMAX];
__device__ int    g_rowcnt[NROWMAX];
__device__ int    g_rows_done;
__device__ int    g_tick;
__device__ int    g_exit;
__device__ double g_loss;

typedef unsigned long long ull;
#define ABSM 0x7FFFFFFF7FFFFFFFull

__device__ __forceinline__ ull add2(ull a, ull b) {
    ull d; asm("add.rn.f32x2 %0,%1,%2;" : "=l"(d) : "l"(a), "l"(b)); return d;
}
__device__ __forceinline__ ull fma2(ull a, ull b, ull c) {
    ull d; asm("fma.rn.f32x2 %0,%1,%2,%3;" : "=l"(d) : "l"(a), "l"(b), "l"(c)); return d;
}
__device__ __forceinline__ ull pack2(float lo, float hi) {
    ull d; asm("mov.b64 %0,{%1,%2};" : "=l"(d) : "f"(lo), "f"(hi)); return d;
}
__device__ __forceinline__ float2 unpack2(ull v) {
    float2 r; asm("mov.b64 {%0,%1},%2;" : "=f"(r.x), "=f"(r.y) : "l"(v)); return r;
}

__device__ __forceinline__ int read_npos(const int* p, int n) {
    int v = p[0];
    if (v < 1) v = 1;
    if (v > n) v = n;
    if (v > QMAX) v = QMAX;
    return v;
}

// One 128q x 256j tile through smem. Depends only on q0/j0/jlim/n.
// outp[k] = 4 * sum relu(c_k + y)^2 over this thread's 32-y slice.
__device__ __forceinline__ void tile_main(
    const float* __restrict__ y_pred, int n,
    int q0, int j0, int jlim,
    float* sY, int tid, int qg, int js, float outp[QPT])
{
    __syncthreads();                                // sY reuse safe
    {
        int j = j0 + tid;                           // NTH == JTILE
        sY[tid] = (j < jlim) ? y_pred[j] : PADV;    // pad: t+|t| == 0 exactly
    }

    ull c2[QPT];
    {
        int qb4 = q0 + qg * QPT;
        float4 cv;
        if (qb4 + QPT <= n) {
            cv = *(const float4*)(y_pred + qb4);
        } else {
            cv.x = (qb4 + 0 < n) ? y_pred[qb4 + 0] : 2.0f;
            cv.y = (qb4 + 1 < n) ? y_pred[qb4 + 1] : 2.0f;
            cv.z = (qb4 + 2 < n) ? y_pred[qb4 + 2] : 2.0f;
            cv.w = (qb4 + 3 < n) ? y_pred[qb4 + 3] : 2.0f;
        }
        float c0 = (qb4 + 0 < n) ? (1.0f - cv.x) : PADV;
        float c1 = (qb4 + 1 < n) ? (1.0f - cv.y) : PADV;
        float c2f = (qb4 + 2 < n) ? (1.0f - cv.z) : PADV;
        float c3 = (qb4 + 3 < n) ? (1.0f - cv.w) : PADV;
        c2[0] = pack2(c0, c0); c2[1] = pack2(c1, c1);
        c2[2] = pack2(c2f, c2f); c2[3] = pack2(c3, c3);
    }
    __syncthreads();

    const ulonglong2* p2 = (const ulonglong2*)(sY + js * JSL); // 128B-aligned
    ull a0[QPT], a1[QPT];
    #pragma unroll
    for (int k = 0; k < QPT; k++) { a0[k] = 0ull; a1[k] = 0ull; }

    #pragma unroll
    for (int u = 0; u < JSL / 4; u++) {             // 8 iters, 4 y each
        ulonglong2 yv = p2[u];                      // LDS.128 broadcast
        #pragma unroll
        for (int k = 0; k < QPT; k++) {
            ull t01 = add2(c2[k], yv.x);
            ull t23 = add2(c2[k], yv.y);
            ull h01 = add2(t01, t01 & ABSM);        // t + |t| = 2*relu(t)
            ull h23 = add2(t23, t23 & ABSM);
            a0[k] = fma2(h01, h01, a0[k]);          // 4*relu(t)^2
            a1[k] = fma2(h23, h23, a1[k]);
        }
    }

    #pragma unroll
    for (int k = 0; k < QPT; k++) {
        float2 v0 = unpack2(a0[k]);
        float2 v1 = unpack2(a1[k]);
        outp[k] = (v0.x + v0.y) + (v1.x + v1.y);    // = 4 * partial
    }
}

__global__ __launch_bounds__(NTH) void k_fused(
    const float* __restrict__ y_pred,
    const float* __restrict__ u_all,
    const float* __restrict__ u_pos,
    const int*   __restrict__ index_s,
    const int*   __restrict__ d_npos,
    float* __restrict__ out, int n, int jb_all, int jsh)
{
    __shared__ float  sY[JTILE];
    __shared__ float  sRed[JS][QTILE];
    __shared__ double sD[JS];
    __shared__ int    sLastRow, sNextT;

    const int tid = threadIdx.x;
    const int qg  = tid & 31;
    const int js  = tid >> 5;

    // issued now, consumed only after the first mainloop
    const int npos = read_npos(d_npos, n);

    int t = blockIdx.x;           // first tile static (speculative prologue)
    while (true) {
        const int qb = (jsh >= 0) ? (t >> jsh) : (t / jb_all);
        const int q0 = qb * QTILE;
        const int j0 = (t - qb * jb_all) * JTILE;

        float p[QPT];
        tile_main(y_pred, n, q0, j0, n, sY, tid, qg, js, p);

        // ---- npos-dependent bookkeeping (load long resolved) ----
        const int nq        = (npos + QTILE - 1) / QTILE;
        const int t_all     = nq * jb_all;
        const int rem       = npos & (JTILE - 1);
        const int npos_base = npos - rem;
        const int tiles     = t_all + (rem ? nq : 0);
        const int target    = jb_all + (rem ? 1 : 0);

        int row = -1, rowq0 = 0;
        bool strad = false;

        if (t >= tiles) {
            // static first tile out of range: discard, steal below
        } else if (t >= t_all) {                    // straddle: redo guarded
            const int qb2 = t - t_all;
            rowq0 = qb2 * QTILE;
            tile_main(y_pred, n, rowq0, npos_base, npos,
                      sY, tid, qg, js, p);
            row = qb2; strad = true;
        } else if (q0 < npos) {
            row = qb; rowq0 = q0;
        }

        if (row >= 0) {
            __syncthreads();                        // protect prev sRed gather
            #pragma unroll
            for (int k = 0; k < QPT; k++)
                sRed[js][qg * QPT + k] = p[k];
            __syncthreads();

            if (tid < QTILE) {
                float s = 0.f;
                #pragma unroll
                for (int r = 0; r < JS; r++) s += sRed[r][tid];
                s *= 0.25f;                         // undo 4x (exact)
                int q = rowq0 + tid;
                if (q < npos) {
                    double sd = (double)s;
                    if (strad) {
                        atomicAdd(&g_Spos[q], sd);
                    } else {
                        atomicAdd(&g_Sall[q], sd);
                        if (j0 + JTILE <= npos)
                            atomicAdd(&g_Spos[q], sd);
                    }
                }
            }

            __syncthreads();
            if (tid == 0) {
                __threadfence();                    // publish deposits
                int old = atomicAdd(&g_rowcnt[row], 1);
                sLastRow = (old == target - 1) ? 1 : 0;
            }
            __syncthreads();

            if (sLastRow) {
                __threadfence();                    // acquire peers' deposits

                const float G    = 0.99f;
                const float OMG  = 1.0f - 0.99f;
                const float invN = 1.0f / (float)n;

                double term = 0.0;
                if (tid < QTILE) {
                    int q = rowq0 + tid;
                    if (q < npos) {
                        float S_all = (float)__ldcg(&g_Sall[q]);
                        float S_pos = (float)__ldcg(&g_Spos[q]);
                        int   id    = index_s[q];
                        float ua = OMG * u_all[id] + G * (S_all * invN);
                        float up = OMG * u_pos[id] + G * (S_pos * invN);
                        float r  = 1.0f / ua;
                        term = (double)((up * S_all * r - S_pos) * r);
                        g_Sall[q] = 0.0;            // reset for next replay
                        g_Spos[q] = 0.0;
                    }
                }
                #pragma unroll
                for (int off = 16; off > 0; off >>= 1)
                    term += __shfl_down_sync(0xffffffffu, term, off);
                if (qg == 0) sD[js] = term;
                __syncthreads();
                if (tid == 0) {
                    double L = 0.0;
                    #pragma unroll
                    for (int w = 0; w < JS; w++) L += sD[w];
                    atomicAdd(&g_loss, L);
                    g_rowcnt[row] = 0;
                    __threadfence();
                    int od = atomicAdd(&g_rows_done, 1);
                    if (od == nq - 1) {             // final row finished
                        __threadfence();
                        double Lf = atomicAdd(&g_loss, 0.0);
                        out[0] = (float)(Lf / ((double)npos * (double)n));
                        atomicExch((unsigned long long*)&g_loss, 0ull);
                        atomicExch(&g_rows_done, 0);
                        // NOTE: g_tick is NOT touched here (R10 bug).
                    }
                }
            }
        }

        // ---- steal next tile (ticket covers t >= NBLK) ----
        if (tid == 0)
            sNextT = NBLK + atomicAdd(&g_tick, 1);
        __syncthreads();
        t = sNextT;
        if (t >= tiles) break;                      // exactly one failed grab
    }

    // ---- race-free ticket reset: last exiter knows all grabs retired ----
    if (tid == 0) {
        __threadfence();                            // order final grab first
        int old = atomicAdd(&g_exit, 1);
        if (old == NBLK - 1) {                      // all blocks' grabs done
            g_tick = 0;
            g_exit = 0;
            __threadfence();                        // publish before exit
        }
    }
}

extern "C" void kernel_launch(void* const* d_in, const int* in_sizes, int n_in,
                              void* d_out, int out_size) {
    const float* y_pred  = (const float*)d_in[0];
    const float* u_all   = (const float*)d_in[2];
    const float* u_pos   = (const float*)d_in[3];
    const int*   index_s = (const int*)  d_in[4];
    const int*   d_npos  = (const int*)  d_in[5];
    int n = in_sizes[0];

    int jb_all = (n + JTILE - 1) / JTILE;
    int jsh = -1;
    if ((jb_all & (jb_all - 1)) == 0) {
        jsh = 0;
        while ((1 << jsh) < jb_all) jsh++;
    }

    k_fused<<<NBLK, NTH>>>(y_pred, u_all, u_pos, index_s, d_npos,
                           (float*)d_out, n, jb_all, jsh);
}